// round 10
// baseline (speedup 1.0000x reference)
#include <cuda_runtime.h>
#include <cuda_bf16.h>
#include <math.h>
#include <stdint.h>

// Problem constants
#define BB 2
#define SS 4096
#define FF 768
#define HH 12
#define DD 64
#define F3 (3 * FF)

// Scratch (alloc-free rule: __device__ globals)
__device__ float g_qkv[(size_t)BB * SS * F3];                    // [B, S, 3F] fp32
__device__ __nv_bfloat16 g_xhi[(size_t)BB * SS * FF];            // x split
__device__ __nv_bfloat16 g_xlo[(size_t)BB * SS * FF];
__device__ __nv_bfloat16 g_wqkvhi[(size_t)F3 * FF];              // Wqkv^T [N=2304][K=768]
__device__ __nv_bfloat16 g_wqkvlo[(size_t)F3 * FF];
__device__ __nv_bfloat16 g_wouthi[(size_t)FF * FF];              // Wout^T [768][768]
__device__ __nv_bfloat16 g_woutlo[(size_t)FF * FF];
__device__ __nv_bfloat16 g_atthi[(size_t)BB * SS * FF];          // attention out split
__device__ __nv_bfloat16 g_attlo[(size_t)BB * SS * FF];

// ============================================================================
// Generic PTX helpers (sm_80+ features only — NO tcgen05/sm_103a-gated ops)
// ============================================================================
__device__ __forceinline__ uint32_t smem_u32(const void* p) {
    uint32_t a;
    asm("{ .reg .u64 t; cvta.to.shared.u64 t, %1; cvt.u32.u64 %0, t; }" : "=r"(a) : "l"(p));
    return a;
}

__device__ __forceinline__ void cp_async16(uint32_t saddr, const void* gaddr) {
    asm volatile("cp.async.cg.shared.global [%0], [%1], 16;" :: "r"(saddr), "l"(gaddr));
}
#define CP_COMMIT() asm volatile("cp.async.commit_group;" ::: "memory")
#define CP_WAIT(n)  asm volatile("cp.async.wait_group %0;" :: "n"(n) : "memory")

__device__ __forceinline__ void ldsm_x4(uint32_t& r0, uint32_t& r1, uint32_t& r2,
                                        uint32_t& r3, uint32_t addr) {
    asm volatile("ldmatrix.sync.aligned.m8n8.x4.shared.b16 {%0,%1,%2,%3}, [%4];"
                 : "=r"(r0), "=r"(r1), "=r"(r2), "=r"(r3) : "r"(addr));
}

__device__ __forceinline__ void mma_bf16(float* d, const uint32_t* a,
                                         uint32_t b0, uint32_t b1) {
    asm volatile(
        "mma.sync.aligned.m16n8k16.row.col.f32.bf16.bf16.f32 "
        "{%0,%1,%2,%3}, {%4,%5,%6,%7}, {%8,%9}, {%0,%1,%2,%3};"
        : "+f"(d[0]), "+f"(d[1]), "+f"(d[2]), "+f"(d[3])
        : "r"(a[0]), "r"(a[1]), "r"(a[2]), "r"(a[3]), "r"(b0), "r"(b1));
}

#define SWZ128(off) ((off) ^ (((off) >> 3) & 0x70))

__device__ __forceinline__ void split_val(float v, __nv_bfloat16& h, __nv_bfloat16& l) {
    h = __float2bfloat16_rn(v);
    l = __float2bfloat16_rn(v - __bfloat162float(h));
}

// ============================================================================
// fp32 -> (hi, lo) bf16 split, same layout. n must be %4.
// ============================================================================
__global__ __launch_bounds__(256) void split_kernel(
    const float* __restrict__ in, __nv_bfloat16* __restrict__ hi,
    __nv_bfloat16* __restrict__ lo, int n4)
{
    int idx = blockIdx.x * 256 + threadIdx.x;
    if (idx >= n4) return;
    float4 v = ((const float4*)in)[idx];
    __nv_bfloat16 h0, h1, h2, h3, l0, l1, l2, l3;
    split_val(v.x, h0, l0); split_val(v.y, h1, l1);
    split_val(v.z, h2, l2); split_val(v.w, h3, l3);
    __nv_bfloat162 ha(h0, h1), hb(h2, h3), la(l0, l1), lb(l2, l3);
    uint2 hu, lu;
    hu.x = *(uint32_t*)&ha; hu.y = *(uint32_t*)&hb;
    lu.x = *(uint32_t*)&la; lu.y = *(uint32_t*)&lb;
    ((uint2*)hi)[idx] = hu;
    ((uint2*)lo)[idx] = lu;
}

// ============================================================================
// fp32 [R][C] -> transposed bf16 hi/lo [C][R]. R,C %32. Block 32x8.
// ============================================================================
__global__ __launch_bounds__(256) void split_transpose(
    const float* __restrict__ in, __nv_bfloat16* __restrict__ hiT,
    __nv_bfloat16* __restrict__ loT, int R, int C)
{
    __shared__ float t[32][33];
    const int tx = threadIdx.x & 31;
    const int ty = threadIdx.x >> 5;   // 0..7
    const int c0 = blockIdx.x * 32;
    const int r0 = blockIdx.y * 32;
#pragma unroll
    for (int j = 0; j < 4; j++)
        t[ty + 8 * j][tx] = in[(size_t)(r0 + ty + 8 * j) * C + c0 + tx];
    __syncthreads();
#pragma unroll
    for (int j = 0; j < 4; j++) {
        float v = t[tx][ty + 8 * j];
        __nv_bfloat16 h, l;
        split_val(v, h, l);
        size_t o = (size_t)(c0 + ty + 8 * j) * R + r0 + tx;
        hiT[o] = h;
        loT[o] = l;
    }
}

// ============================================================================
// mma.sync split-bf16 GEMM: C[M,N] = (Ahi+Alo)[M,K] @ (Bhi+Blo)[N,K]^T + bias
// A, B K-major bf16. 128x128 CTA tile, 256 threads (8 warps, 2n x 4m).
// Warp tile 32(m) x 64(n). K-slab 64, cp.async double buffered, SW128 smem.
// 3 compensated MMAs per position (hi*hi + hi*lo + lo*hi).
// ============================================================================
#define GEMM_SMEM (2 * 65536)

__global__ __launch_bounds__(256, 1) void gemm_tc(
    const __nv_bfloat16* __restrict__ Ahi, const __nv_bfloat16* __restrict__ Alo,
    const __nv_bfloat16* __restrict__ Bhi, const __nv_bfloat16* __restrict__ Blo,
    const float* __restrict__ bias, float* __restrict__ C,
    int M, int N, int K)
{
    extern __shared__ __align__(1024) char sm[];
    const uint32_t smem_base = smem_u32(sm);
    const int tid  = threadIdx.x;
    const int wid  = tid >> 5;
    const int lane = tid & 31;
    const int m0 = blockIdx.y * 128;
    const int n0 = blockIdx.x * 128;
    const int wm = (wid & 3) * 32;   // warp m offset within tile
    const int wn = (wid >> 2) * 64;  // warp n offset within tile

    const int nslab = K >> 6;  // K/64

    // slab loader: 4 operand tiles [128 rows][64 bf16] SW128, cp.async 16B
    auto load_slab = [&](int s) {
        const uint32_t base = smem_base + (uint32_t)(s & 1) * 65536;
        const int k0 = s << 6;
#pragma unroll
        for (int it = 0; it < 4; it++) {
            int idx = tid + it * 256;           // 0..1023
            int row = idx >> 3;
            int ch  = idx & 7;                   // 16B chunk within 128B row
            uint32_t sw = SWZ128((uint32_t)(row * 128 + ch * 16));
            size_t ga = (size_t)(m0 + row) * K + k0 + ch * 8;
            size_t gb = (size_t)(n0 + row) * K + k0 + ch * 8;
            cp_async16(base + sw,         Ahi + ga);
            cp_async16(base + 16384 + sw, Alo + ga);
            cp_async16(base + 32768 + sw, Bhi + gb);
            cp_async16(base + 49152 + sw, Blo + gb);
        }
    };

    float acc[2][8][4];
#pragma unroll
    for (int mt = 0; mt < 2; mt++)
#pragma unroll
        for (int nt = 0; nt < 8; nt++)
#pragma unroll
            for (int e = 0; e < 4; e++) acc[mt][nt][e] = 0.f;

    // ldmatrix per-lane address components (within a [128][64bf16] SW128 tile)
    // A (x4, m16 x k16): rows m..m+15 at kb, kb+16
    const int a_row = lane & 15;
    const int a_kb  = (lane >> 4) << 4;           // 0 or 16 bytes
    // B (x4, two n8 tiles x k16): lanes 0-7 n0-7@k0 | 8-15 n0-7@k16 | 16-23 n8-15@k0 | 24-31 n8-15@k16
    const int b_row = ((lane >> 4) << 3) + (lane & 7);
    const int b_kb  = ((lane >> 3) & 1) << 4;

    load_slab(0);
    CP_COMMIT();

    for (int s = 0; s < nslab; s++) {
        if (s + 1 < nslab) {
            load_slab(s + 1);
            CP_COMMIT();
            CP_WAIT(1);
        } else {
            CP_WAIT(0);
        }
        __syncthreads();

        const uint32_t base = smem_base + (uint32_t)(s & 1) * 65536;
#pragma unroll
        for (int ks = 0; ks < 4; ks++) {
            const int kbyte = ks * 32;
            uint32_t ah[2][4], al[2][4], bh[4][4], bl[4][4];
#pragma unroll
            for (int mt = 0; mt < 2; mt++) {
                uint32_t off = SWZ128((uint32_t)((wm + mt * 16 + a_row) * 128 + kbyte + a_kb));
                ldsm_x4(ah[mt][0], ah[mt][1], ah[mt][2], ah[mt][3], base + off);
                ldsm_x4(al[mt][0], al[mt][1], al[mt][2], al[mt][3], base + 16384 + off);
            }
#pragma unroll
            for (int nt2 = 0; nt2 < 4; nt2++) {
                uint32_t off = SWZ128((uint32_t)((wn + nt2 * 16 + b_row) * 128 + kbyte + b_kb));
                ldsm_x4(bh[nt2][0], bh[nt2][1], bh[nt2][2], bh[nt2][3], base + 32768 + off);
                ldsm_x4(bl[nt2][0], bl[nt2][1], bl[nt2][2], bl[nt2][3], base + 49152 + off);
            }
#pragma unroll
            for (int mt = 0; mt < 2; mt++)
#pragma unroll
                for (int nt = 0; nt < 8; nt++) {
                    const int q = nt >> 1, r = (nt & 1) << 1;
                    mma_bf16(acc[mt][nt], ah[mt], bh[q][r], bh[q][r + 1]);  // hi*hi
                    mma_bf16(acc[mt][nt], ah[mt], bl[q][r], bl[q][r + 1]);  // hi*lo
                    mma_bf16(acc[mt][nt], al[mt], bh[q][r], bh[q][r + 1]);  // lo*hi
                }
        }
        __syncthreads();  // all warps done reading buffer s before slab s+2 load
    }

    // Epilogue: acc fragment -> C with bias. d0,d1: row=lane/4, col=2*(lane%4);
    // d2,d3: row+8.
    const int erow = lane >> 2;
    const int ecol = (lane & 3) << 1;
#pragma unroll
    for (int mt = 0; mt < 2; mt++) {
#pragma unroll
        for (int nt = 0; nt < 8; nt++) {
            const int gc = n0 + wn + nt * 8 + ecol;
            const int gr = m0 + wm + mt * 16 + erow;
            float2 v0, v1;
            v0.x = acc[mt][nt][0] + bias[gc];
            v0.y = acc[mt][nt][1] + bias[gc + 1];
            v1.x = acc[mt][nt][2] + bias[gc];
            v1.y = acc[mt][nt][3] + bias[gc + 1];
            *(float2*)(C + (size_t)gr * N + gc)       = v0;
            *(float2*)(C + (size_t)(gr + 8) * N + gc) = v1;
        }
    }
}

// ============================================================================
// Flash attention (fp32 SIMT, round-3 proven); epilogue writes bf16 hi/lo.
// ============================================================================
#define ATT_SMEM (4 * 64 * 65 * sizeof(float))

__global__ __launch_bounds__(256) void flash_attn(
    const float* __restrict__ qkv, const unsigned char* __restrict__ pad,
    __nv_bfloat16* __restrict__ outhi, __nv_bfloat16* __restrict__ outlo)
{
    extern __shared__ float smf[];
    float* Qs = smf;
    float* Ks = Qs + 64 * 65;
    float* Vs = Ks + 64 * 65;
    float* Ps = Vs + 64 * 65;
    __shared__ unsigned char padf[64];

    const int qt = (gridDim.x - 1) - blockIdx.x;
    const int h  = blockIdx.y;
    const int b  = blockIdx.z;
    const int tid = threadIdx.x;
    const int ty  = tid >> 4;
    const int tx  = tid & 15;
    const float scale = 0.125f;
    const size_t base = (size_t)b * SS * F3;
    const int q0 = qt * 64;

    for (int i = tid; i < 64 * 16; i += 256) {
        int r  = i >> 4;
        int c4 = (i & 15) << 2;
        float4 v = *(const float4*)(qkv + base + (size_t)(q0 + r) * F3 + h * DD + c4);
        Qs[r * 65 + c4 + 0] = v.x * scale;
        Qs[r * 65 + c4 + 1] = v.y * scale;
        Qs[r * 65 + c4 + 2] = v.z * scale;
        Qs[r * 65 + c4 + 3] = v.w * scale;
    }

    float m[4], l[4], o[4][4];
#pragma unroll
    for (int i = 0; i < 4; i++) {
        m[i] = -1e30f; l[i] = 0.f;
#pragma unroll
        for (int j = 0; j < 4; j++) o[i][j] = 0.f;
    }

    for (int kt = 0; kt <= qt; kt++) {
        const int k0 = kt * 64;
        __syncthreads();
        for (int i = tid; i < 64 * 16; i += 256) {
            int r  = i >> 4;
            int c4 = (i & 15) << 2;
            float4 kv = *(const float4*)(qkv + base + (size_t)(k0 + r) * F3 + FF + h * DD + c4);
            Ks[r * 65 + c4 + 0] = kv.x;
            Ks[r * 65 + c4 + 1] = kv.y;
            Ks[r * 65 + c4 + 2] = kv.z;
            Ks[r * 65 + c4 + 3] = kv.w;
            float4 vv = *(const float4*)(qkv + base + (size_t)(k0 + r) * F3 + 2 * FF + h * DD + c4);
            Vs[r * 65 + c4 + 0] = vv.x;
            Vs[r * 65 + c4 + 1] = vv.y;
            Vs[r * 65 + c4 + 2] = vv.z;
            Vs[r * 65 + c4 + 3] = vv.w;
        }
        if (tid < 64) padf[tid] = pad[(size_t)b * SS + k0 + tid];
        __syncthreads();

        float acc[4][4];
#pragma unroll
        for (int i = 0; i < 4; i++)
#pragma unroll
            for (int j = 0; j < 4; j++) acc[i][j] = 0.f;

#pragma unroll 8
        for (int d = 0; d < 64; d++) {
            float ar[4], br[4];
#pragma unroll
            for (int i = 0; i < 4; i++) ar[i] = Qs[(4 * ty + i) * 65 + d];
#pragma unroll
            for (int j = 0; j < 4; j++) br[j] = Ks[(4 * tx + j) * 65 + d];
#pragma unroll
            for (int i = 0; i < 4; i++)
#pragma unroll
                for (int j = 0; j < 4; j++) acc[i][j] += ar[i] * br[j];
        }

        const bool diag = (kt == qt);
#pragma unroll
        for (int j = 0; j < 4; j++) {
            const int kj = 4 * tx + j;
            const bool padded = padf[kj] != 0;
#pragma unroll
            for (int i = 0; i < 4; i++) {
                const int qi = 4 * ty + i;
                if ((diag && kj > qi) || padded) acc[i][j] = -1e30f;
            }
        }

        float mnew[4];
#pragma unroll
        for (int i = 0; i < 4; i++) {
            float rm = fmaxf(fmaxf(acc[i][0], acc[i][1]), fmaxf(acc[i][2], acc[i][3]));
#pragma unroll
            for (int off = 8; off >= 1; off >>= 1)
                rm = fmaxf(rm, __shfl_xor_sync(0xffffffffu, rm, off));
            mnew[i] = fmaxf(m[i], rm);
            float alpha = __expf(m[i] - mnew[i]);
            m[i] = mnew[i];
            float rs = 0.f;
#pragma unroll
            for (int j = 0; j < 4; j++) {
                float p = __expf(acc[i][j] - mnew[i]);
                acc[i][j] = p;
                rs += p;
            }
#pragma unroll
            for (int off = 8; off >= 1; off >>= 1)
                rs += __shfl_xor_sync(0xffffffffu, rs, off);
            l[i] = l[i] * alpha + rs;
#pragma unroll
            for (int j = 0; j < 4; j++) o[i][j] *= alpha;
        }

#pragma unroll
        for (int i = 0; i < 4; i++)
#pragma unroll
            for (int j = 0; j < 4; j++)
                Ps[(4 * ty + i) * 65 + 4 * tx + j] = acc[i][j];
        __syncthreads();

#pragma unroll 8
        for (int n = 0; n < 64; n++) {
            float ar[4], br[4];
#pragma unroll
            for (int i = 0; i < 4; i++) ar[i] = Ps[(4 * ty + i) * 65 + n];
#pragma unroll
            for (int j = 0; j < 4; j++) br[j] = Vs[n * 65 + 4 * tx + j];
#pragma unroll
            for (int i = 0; i < 4; i++)
#pragma unroll
                for (int j = 0; j < 4; j++) o[i][j] += ar[i] * br[j];
        }
    }

    // Epilogue: normalize + split to bf16 hi/lo
#pragma unroll
    for (int i = 0; i < 4; i++) {
        const float invl = 1.0f / l[i];
        __nv_bfloat16 hh[4], ll[4];
#pragma unroll
        for (int j = 0; j < 4; j++) {
            float v = o[i][j] * invl;
            split_val(v, hh[j], ll[j]);
        }
        __nv_bfloat162 ha(hh[0], hh[1]), hb(hh[2], hh[3]);
        __nv_bfloat162 la(ll[0], ll[1]), lb(ll[2], ll[3]);
        uint2 hu, lu;
        hu.x = *(uint32_t*)&ha; hu.y = *(uint32_t*)&hb;
        lu.x = *(uint32_t*)&la; lu.y = *(uint32_t*)&lb;
        size_t off = (size_t)b * SS * FF + (size_t)(q0 + 4 * ty + i) * FF + h * DD + 4 * tx;
        *(uint2*)(outhi + off) = hu;
        *(uint2*)(outlo + off) = lu;
    }
}

// ============================================================================
extern "C" void kernel_launch(void* const* d_in, const int* in_sizes, int n_in,
                              void* d_out, int out_size)
{
    const float*         x    = (const float*)d_in[0];
    const unsigned char* pad  = (const unsigned char*)d_in[1];
    const float*         Wqkv = (const float*)d_in[2];
    const float*         bqkv = (const float*)d_in[3];
    const float*         Wout = (const float*)d_in[4];
    const float*         bout = (const float*)d_in[5];
    float*               out  = (float*)d_out;

    float *qkv_ptr;
    __nv_bfloat16 *xhi, *xlo, *wqh, *wql, *woh, *wol, *ahi, *alo;
    cudaGetSymbolAddress((void**)&qkv_ptr, g_qkv);
    cudaGetSymbolAddress((void**)&xhi, g_xhi);
    cudaGetSymbolAddress((void**)&xlo, g_xlo);
    cudaGetSymbolAddress((void**)&wqh, g_wqkvhi);
    cudaGetSymbolAddress((void**)&wql, g_wqkvlo);
    cudaGetSymbolAddress((void**)&woh, g_wouthi);
    cudaGetSymbolAddress((void**)&wol, g_woutlo);
    cudaGetSymbolAddress((void**)&ahi, g_atthi);
    cudaGetSymbolAddress((void**)&alo, g_attlo);

    cudaFuncSetAttribute(gemm_tc, cudaFuncAttributeMaxDynamicSharedMemorySize, GEMM_SMEM);
    cudaFuncSetAttribute(flash_attn, cudaFuncAttributeMaxDynamicSharedMemorySize, (int)ATT_SMEM);

    // 0) splits
    {
        int n4 = (BB * SS * FF) / 4;
        split_kernel<<<(n4 + 255) / 256, 256>>>(x, xhi, xlo, n4);
        dim3 g1(F3 / 32, FF / 32);
        split_transpose<<<g1, 256>>>(Wqkv, wqh, wql, FF, F3);
        dim3 g2(FF / 32, FF / 32);
        split_transpose<<<g2, 256>>>(Wout, woh, wol, FF, FF);
    }

    // 1) qkv = x @ Wqkv + bqkv (mma.sync, split-bf16)
    {
        dim3 grid(F3 / 128, (BB * SS) / 128);
        gemm_tc<<<grid, 256, GEMM_SMEM>>>(xhi, xlo, wqh, wql, bqkv, qkv_ptr,
                                          BB * SS, F3, FF);
    }

    // 2) flash attention -> bf16 hi/lo
    {
        dim3 grid(SS / 64, HH, BB);
        flash_attn<<<grid, 256, ATT_SMEM>>>(qkv_ptr, pad, ahi, alo);
    }

    // 3) out = att @ Wout + bout (mma.sync, split-bf16)
    {
        dim3 grid(FF / 128, (BB * SS) / 128);
        gemm_tc<<<grid, 256, GEMM_SMEM>>>(ahi, alo, woh, wol, bout, out,
                                          BB * SS, FF, FF);
    }
}

// round 11
// speedup vs baseline: 1.0051x; 1.0051x over previous
#include <cuda_runtime.h>
#include <cuda_bf16.h>
#include <math.h>
#include <stdint.h>

// Problem constants
#define BB 2
#define SS 4096
#define FF 768
#define HH 12
#define DD 64
#define F3 (3 * FF)

// Scratch (alloc-free rule: __device__ globals)
__device__ float g_qkv[(size_t)BB * SS * F3];                    // [B, S, 3F] fp32
__device__ __nv_bfloat16 g_xhi[(size_t)BB * SS * FF];            // x split
__device__ __nv_bfloat16 g_xlo[(size_t)BB * SS * FF];
__device__ __nv_bfloat16 g_wqkvhi[(size_t)F3 * FF];              // Wqkv^T [N=2304][K=768]
__device__ __nv_bfloat16 g_wqkvlo[(size_t)F3 * FF];
__device__ __nv_bfloat16 g_wouthi[(size_t)FF * FF];              // Wout^T [768][768]
__device__ __nv_bfloat16 g_woutlo[(size_t)FF * FF];
__device__ __nv_bfloat16 g_atthi[(size_t)BB * SS * FF];          // attention out split
__device__ __nv_bfloat16 g_attlo[(size_t)BB * SS * FF];

// ============================================================================
// Generic PTX helpers (sm_80+ features only — NO tcgen05/sm_103a-gated ops)
// ============================================================================
__device__ __forceinline__ uint32_t smem_u32(const void* p) {
    uint32_t a;
    asm("{ .reg .u64 t; cvta.to.shared.u64 t, %1; cvt.u32.u64 %0, t; }" : "=r"(a) : "l"(p));
    return a;
}

__device__ __forceinline__ void cp_async16(uint32_t saddr, const void* gaddr) {
    asm volatile("cp.async.cg.shared.global [%0], [%1], 16;" :: "r"(saddr), "l"(gaddr));
}
#define CP_COMMIT() asm volatile("cp.async.commit_group;" ::: "memory")
#define CP_WAIT(n)  asm volatile("cp.async.wait_group %0;" :: "n"(n) : "memory")

__device__ __forceinline__ void ldsm_x4(uint32_t& r0, uint32_t& r1, uint32_t& r2,
                                        uint32_t& r3, uint32_t addr) {
    asm volatile("ldmatrix.sync.aligned.m8n8.x4.shared.b16 {%0,%1,%2,%3}, [%4];"
                 : "=r"(r0), "=r"(r1), "=r"(r2), "=r"(r3) : "r"(addr));
}

__device__ __forceinline__ void mma_bf16(float* d, const uint32_t* a,
                                         uint32_t b0, uint32_t b1) {
    asm volatile(
        "mma.sync.aligned.m16n8k16.row.col.f32.bf16.bf16.f32 "
        "{%0,%1,%2,%3}, {%4,%5,%6,%7}, {%8,%9}, {%0,%1,%2,%3};"
        : "+f"(d[0]), "+f"(d[1]), "+f"(d[2]), "+f"(d[3])
        : "r"(a[0]), "r"(a[1]), "r"(a[2]), "r"(a[3]), "r"(b0), "r"(b1));
}

#define SWZ128(off) ((off) ^ (((off) >> 3) & 0x70))

__device__ __forceinline__ void split_val(float v, __nv_bfloat16& h, __nv_bfloat16& l) {
    h = __float2bfloat16_rn(v);
    l = __float2bfloat16_rn(v - __bfloat162float(h));
}

// ============================================================================
// fp32 -> (hi, lo) bf16 split, same layout. n must be %4.
// ============================================================================
__global__ __launch_bounds__(256) void split_kernel(
    const float* __restrict__ in, __nv_bfloat16* __restrict__ hi,
    __nv_bfloat16* __restrict__ lo, int n4)
{
    int idx = blockIdx.x * 256 + threadIdx.x;
    if (idx >= n4) return;
    float4 v = ((const float4*)in)[idx];
    __nv_bfloat16 h0, h1, h2, h3, l0, l1, l2, l3;
    split_val(v.x, h0, l0); split_val(v.y, h1, l1);
    split_val(v.z, h2, l2); split_val(v.w, h3, l3);
    __nv_bfloat162 ha(h0, h1), hb(h2, h3), la(l0, l1), lb(l2, l3);
    uint2 hu, lu;
    hu.x = *(uint32_t*)&ha; hu.y = *(uint32_t*)&hb;
    lu.x = *(uint32_t*)&la; lu.y = *(uint32_t*)&lb;
    ((uint2*)hi)[idx] = hu;
    ((uint2*)lo)[idx] = lu;
}

// ============================================================================
// fp32 [R][C] -> transposed bf16 hi/lo [C][R]. R,C %32. Block 32x8.
// ============================================================================
__global__ __launch_bounds__(256) void split_transpose(
    const float* __restrict__ in, __nv_bfloat16* __restrict__ hiT,
    __nv_bfloat16* __restrict__ loT, int R, int C)
{
    __shared__ float t[32][33];
    const int tx = threadIdx.x & 31;
    const int ty = threadIdx.x >> 5;   // 0..7
    const int c0 = blockIdx.x * 32;
    const int r0 = blockIdx.y * 32;
#pragma unroll
    for (int j = 0; j < 4; j++)
        t[ty + 8 * j][tx] = in[(size_t)(r0 + ty + 8 * j) * C + c0 + tx];
    __syncthreads();
#pragma unroll
    for (int j = 0; j < 4; j++) {
        float v = t[tx][ty + 8 * j];
        __nv_bfloat16 h, l;
        split_val(v, h, l);
        size_t o = (size_t)(c0 + ty + 8 * j) * R + r0 + tx;
        hiT[o] = h;
        loT[o] = l;
    }
}

// ============================================================================
// mma.sync split-bf16 GEMM: C[M,N] = (Ahi+Alo)[M,K] @ (Bhi+Blo)[N,K]^T + bias
// A, B K-major bf16. 128x128 CTA tile, 256 threads (8 warps, 2n x 4m).
// Warp tile 32(m) x 64(n). K-slab 64, cp.async double buffered, SW128 smem.
// 3 compensated MMAs per position (hi*hi + hi*lo + lo*hi).
// ============================================================================
#define GEMM_SMEM (2 * 65536)

__global__ __launch_bounds__(256, 1) void gemm_tc(
    const __nv_bfloat16* __restrict__ Ahi, const __nv_bfloat16* __restrict__ Alo,
    const __nv_bfloat16* __restrict__ Bhi, const __nv_bfloat16* __restrict__ Blo,
    const float* __restrict__ bias, float* __restrict__ C,
    int M, int N, int K)
{
    extern __shared__ __align__(1024) char sm[];
    const uint32_t smem_base = smem_u32(sm);
    const int tid  = threadIdx.x;
    const int wid  = tid >> 5;
    const int lane = tid & 31;
    const int m0 = blockIdx.y * 128;
    const int n0 = blockIdx.x * 128;
    const int wm = (wid & 3) * 32;   // warp m offset within tile
    const int wn = (wid >> 2) * 64;  // warp n offset within tile

    const int nslab = K >> 6;  // K/64

    // slab loader: 4 operand tiles [128 rows][64 bf16] SW128, cp.async 16B
    auto load_slab = [&](int s) {
        const uint32_t base = smem_base + (uint32_t)(s & 1) * 65536;
        const int k0 = s << 6;
#pragma unroll
        for (int it = 0; it < 4; it++) {
            int idx = tid + it * 256;           // 0..1023
            int row = idx >> 3;
            int ch  = idx & 7;                   // 16B chunk within 128B row
            uint32_t sw = SWZ128((uint32_t)(row * 128 + ch * 16));
            size_t ga = (size_t)(m0 + row) * K + k0 + ch * 8;
            size_t gb = (size_t)(n0 + row) * K + k0 + ch * 8;
            cp_async16(base + sw,         Ahi + ga);
            cp_async16(base + 16384 + sw, Alo + ga);
            cp_async16(base + 32768 + sw, Bhi + gb);
            cp_async16(base + 49152 + sw, Blo + gb);
        }
    };

    float acc[2][8][4];
#pragma unroll
    for (int mt = 0; mt < 2; mt++)
#pragma unroll
        for (int nt = 0; nt < 8; nt++)
#pragma unroll
            for (int e = 0; e < 4; e++) acc[mt][nt][e] = 0.f;

    // ldmatrix per-lane address components (within a [128][64bf16] SW128 tile)
    // A (x4, m16 x k16): rows m..m+15 at kb, kb+16
    const int a_row = lane & 15;
    const int a_kb  = (lane >> 4) << 4;           // 0 or 16 bytes
    // B (x4, two n8 tiles x k16): lanes 0-7 n0-7@k0 | 8-15 n0-7@k16 | 16-23 n8-15@k0 | 24-31 n8-15@k16
    const int b_row = ((lane >> 4) << 3) + (lane & 7);
    const int b_kb  = ((lane >> 3) & 1) << 4;

    load_slab(0);
    CP_COMMIT();

    for (int s = 0; s < nslab; s++) {
        if (s + 1 < nslab) {
            load_slab(s + 1);
            CP_COMMIT();
            CP_WAIT(1);
        } else {
            CP_WAIT(0);
        }
        __syncthreads();

        const uint32_t base = smem_base + (uint32_t)(s & 1) * 65536;
#pragma unroll
        for (int ks = 0; ks < 4; ks++) {
            const int kbyte = ks * 32;
            uint32_t ah[2][4], al[2][4], bh[4][4], bl[4][4];
#pragma unroll
            for (int mt = 0; mt < 2; mt++) {
                uint32_t off = SWZ128((uint32_t)((wm + mt * 16 + a_row) * 128 + kbyte + a_kb));
                ldsm_x4(ah[mt][0], ah[mt][1], ah[mt][2], ah[mt][3], base + off);
                ldsm_x4(al[mt][0], al[mt][1], al[mt][2], al[mt][3], base + 16384 + off);
            }
#pragma unroll
            for (int nt2 = 0; nt2 < 4; nt2++) {
                uint32_t off = SWZ128((uint32_t)((wn + nt2 * 16 + b_row) * 128 + kbyte + b_kb));
                ldsm_x4(bh[nt2][0], bh[nt2][1], bh[nt2][2], bh[nt2][3], base + 32768 + off);
                ldsm_x4(bl[nt2][0], bl[nt2][1], bl[nt2][2], bl[nt2][3], base + 49152 + off);
            }
#pragma unroll
            for (int mt = 0; mt < 2; mt++)
#pragma unroll
                for (int nt = 0; nt < 8; nt++) {
                    const int q = nt >> 1, r = (nt & 1) << 1;
                    mma_bf16(acc[mt][nt], ah[mt], bh[q][r], bh[q][r + 1]);  // hi*hi
                    mma_bf16(acc[mt][nt], ah[mt], bl[q][r], bl[q][r + 1]);  // hi*lo
                    mma_bf16(acc[mt][nt], al[mt], bh[q][r], bh[q][r + 1]);  // lo*hi
                }
        }
        __syncthreads();  // all warps done reading buffer s before slab s+2 load
    }

    // Epilogue: acc fragment -> C with bias. d0,d1: row=lane/4, col=2*(lane%4);
    // d2,d3: row+8.
    const int erow = lane >> 2;
    const int ecol = (lane & 3) << 1;
#pragma unroll
    for (int mt = 0; mt < 2; mt++) {
#pragma unroll
        for (int nt = 0; nt < 8; nt++) {
            const int gc = n0 + wn + nt * 8 + ecol;
            const int gr = m0 + wm + mt * 16 + erow;
            float2 v0, v1;
            v0.x = acc[mt][nt][0] + bias[gc];
            v0.y = acc[mt][nt][1] + bias[gc + 1];
            v1.x = acc[mt][nt][2] + bias[gc];
            v1.y = acc[mt][nt][3] + bias[gc + 1];
            *(float2*)(C + (size_t)gr * N + gc)       = v0;
            *(float2*)(C + (size_t)(gr + 8) * N + gc) = v1;
        }
    }
}

// ============================================================================
// Flash attention (fp32 SIMT, round-3 proven); epilogue writes bf16 hi/lo.
// ============================================================================
#define ATT_SMEM (4 * 64 * 65 * sizeof(float))

__global__ __launch_bounds__(256) void flash_attn(
    const float* __restrict__ qkv, const unsigned char* __restrict__ pad,
    __nv_bfloat16* __restrict__ outhi, __nv_bfloat16* __restrict__ outlo)
{
    extern __shared__ float smf[];
    float* Qs = smf;
    float* Ks = Qs + 64 * 65;
    float* Vs = Ks + 64 * 65;
    float* Ps = Vs + 64 * 65;
    __shared__ unsigned char padf[64];

    const int qt = (gridDim.x - 1) - blockIdx.x;
    const int h  = blockIdx.y;
    const int b  = blockIdx.z;
    const int tid = threadIdx.x;
    const int ty  = tid >> 4;
    const int tx  = tid & 15;
    const float scale = 0.125f;
    const size_t base = (size_t)b * SS * F3;
    const int q0 = qt * 64;

    for (int i = tid; i < 64 * 16; i += 256) {
        int r  = i >> 4;
        int c4 = (i & 15) << 2;
        float4 v = *(const float4*)(qkv + base + (size_t)(q0 + r) * F3 + h * DD + c4);
        Qs[r * 65 + c4 + 0] = v.x * scale;
        Qs[r * 65 + c4 + 1] = v.y * scale;
        Qs[r * 65 + c4 + 2] = v.z * scale;
        Qs[r * 65 + c4 + 3] = v.w * scale;
    }

    float m[4], l[4], o[4][4];
#pragma unroll
    for (int i = 0; i < 4; i++) {
        m[i] = -1e30f; l[i] = 0.f;
#pragma unroll
        for (int j = 0; j < 4; j++) o[i][j] = 0.f;
    }

    for (int kt = 0; kt <= qt; kt++) {
        const int k0 = kt * 64;
        __syncthreads();
        for (int i = tid; i < 64 * 16; i += 256) {
            int r  = i >> 4;
            int c4 = (i & 15) << 2;
            float4 kv = *(const float4*)(qkv + base + (size_t)(k0 + r) * F3 + FF + h * DD + c4);
            Ks[r * 65 + c4 + 0] = kv.x;
            Ks[r * 65 + c4 + 1] = kv.y;
            Ks[r * 65 + c4 + 2] = kv.z;
            Ks[r * 65 + c4 + 3] = kv.w;
            float4 vv = *(const float4*)(qkv + base + (size_t)(k0 + r) * F3 + 2 * FF + h * DD + c4);
            Vs[r * 65 + c4 + 0] = vv.x;
            Vs[r * 65 + c4 + 1] = vv.y;
            Vs[r * 65 + c4 + 2] = vv.z;
            Vs[r * 65 + c4 + 3] = vv.w;
        }
        if (tid < 64) padf[tid] = pad[(size_t)b * SS + k0 + tid];
        __syncthreads();

        float acc[4][4];
#pragma unroll
        for (int i = 0; i < 4; i++)
#pragma unroll
            for (int j = 0; j < 4; j++) acc[i][j] = 0.f;

#pragma unroll 8
        for (int d = 0; d < 64; d++) {
            float ar[4], br[4];
#pragma unroll
            for (int i = 0; i < 4; i++) ar[i] = Qs[(4 * ty + i) * 65 + d];
#pragma unroll
            for (int j = 0; j < 4; j++) br[j] = Ks[(4 * tx + j) * 65 + d];
#pragma unroll
            for (int i = 0; i < 4; i++)
#pragma unroll
                for (int j = 0; j < 4; j++) acc[i][j] += ar[i] * br[j];
        }

        const bool diag = (kt == qt);
#pragma unroll
        for (int j = 0; j < 4; j++) {
            const int kj = 4 * tx + j;
            const bool padded = padf[kj] != 0;
#pragma unroll
            for (int i = 0; i < 4; i++) {
                const int qi = 4 * ty + i;
                if ((diag && kj > qi) || padded) acc[i][j] = -1e30f;
            }
        }

        float mnew[4];
#pragma unroll
        for (int i = 0; i < 4; i++) {
            float rm = fmaxf(fmaxf(acc[i][0], acc[i][1]), fmaxf(acc[i][2], acc[i][3]));
#pragma unroll
            for (int off = 8; off >= 1; off >>= 1)
                rm = fmaxf(rm, __shfl_xor_sync(0xffffffffu, rm, off));
            mnew[i] = fmaxf(m[i], rm);
            float alpha = __expf(m[i] - mnew[i]);
            m[i] = mnew[i];
            float rs = 0.f;
#pragma unroll
            for (int j = 0; j < 4; j++) {
                float p = __expf(acc[i][j] - mnew[i]);
                acc[i][j] = p;
                rs += p;
            }
#pragma unroll
            for (int off = 8; off >= 1; off >>= 1)
                rs += __shfl_xor_sync(0xffffffffu, rs, off);
            l[i] = l[i] * alpha + rs;
#pragma unroll
            for (int j = 0; j < 4; j++) o[i][j] *= alpha;
        }

#pragma unroll
        for (int i = 0; i < 4; i++)
#pragma unroll
            for (int j = 0; j < 4; j++)
                Ps[(4 * ty + i) * 65 + 4 * tx + j] = acc[i][j];
        __syncthreads();

#pragma unroll 8
        for (int n = 0; n < 64; n++) {
            float ar[4], br[4];
#pragma unroll
            for (int i = 0; i < 4; i++) ar[i] = Ps[(4 * ty + i) * 65 + n];
#pragma unroll
            for (int j = 0; j < 4; j++) br[j] = Vs[n * 65 + 4 * tx + j];
#pragma unroll
            for (int i = 0; i < 4; i++)
#pragma unroll
                for (int j = 0; j < 4; j++) o[i][j] += ar[i] * br[j];
        }
    }

    // Epilogue: normalize + split to bf16 hi/lo
#pragma unroll
    for (int i = 0; i < 4; i++) {
        const float invl = 1.0f / l[i];
        __nv_bfloat16 hh[4], ll[4];
#pragma unroll
        for (int j = 0; j < 4; j++) {
            float v = o[i][j] * invl;
            split_val(v, hh[j], ll[j]);
        }
        __nv_bfloat162 ha(hh[0], hh[1]), hb(hh[2], hh[3]);
        __nv_bfloat162 la(ll[0], ll[1]), lb(ll[2], ll[3]);
        uint2 hu, lu;
        hu.x = *(uint32_t*)&ha; hu.y = *(uint32_t*)&hb;
        lu.x = *(uint32_t*)&la; lu.y = *(uint32_t*)&lb;
        size_t off = (size_t)b * SS * FF + (size_t)(q0 + 4 * ty + i) * FF + h * DD + 4 * tx;
        *(uint2*)(outhi + off) = hu;
        *(uint2*)(outlo + off) = lu;
    }
}

// ============================================================================
extern "C" void kernel_launch(void* const* d_in, const int* in_sizes, int n_in,
                              void* d_out, int out_size)
{
    const float*         x    = (const float*)d_in[0];
    const unsigned char* pad  = (const unsigned char*)d_in[1];
    const float*         Wqkv = (const float*)d_in[2];
    const float*         bqkv = (const float*)d_in[3];
    const float*         Wout = (const float*)d_in[4];
    const float*         bout = (const float*)d_in[5];
    float*               out  = (float*)d_out;

    float *qkv_ptr;
    __nv_bfloat16 *xhi, *xlo, *wqh, *wql, *woh, *wol, *ahi, *alo;
    cudaGetSymbolAddress((void**)&qkv_ptr, g_qkv);
    cudaGetSymbolAddress((void**)&xhi, g_xhi);
    cudaGetSymbolAddress((void**)&xlo, g_xlo);
    cudaGetSymbolAddress((void**)&wqh, g_wqkvhi);
    cudaGetSymbolAddress((void**)&wql, g_wqkvlo);
    cudaGetSymbolAddress((void**)&woh, g_wouthi);
    cudaGetSymbolAddress((void**)&wol, g_woutlo);
    cudaGetSymbolAddress((void**)&ahi, g_atthi);
    cudaGetSymbolAddress((void**)&alo, g_attlo);

    cudaFuncSetAttribute(gemm_tc, cudaFuncAttributeMaxDynamicSharedMemorySize, GEMM_SMEM);
    cudaFuncSetAttribute(flash_attn, cudaFuncAttributeMaxDynamicSharedMemorySize, (int)ATT_SMEM);

    // 0) splits
    {
        int n4 = (BB * SS * FF) / 4;
        split_kernel<<<(n4 + 255) / 256, 256>>>(x, xhi, xlo, n4);
        dim3 g1(F3 / 32, FF / 32);
        split_transpose<<<g1, 256>>>(Wqkv, wqh, wql, FF, F3);
        dim3 g2(FF / 32, FF / 32);
        split_transpose<<<g2, 256>>>(Wout, woh, wol, FF, FF);
    }

    // 1) qkv = x @ Wqkv + bqkv (mma.sync, split-bf16)
    {
        dim3 grid(F3 / 128, (BB * SS) / 128);
        gemm_tc<<<grid, 256, GEMM_SMEM>>>(xhi, xlo, wqh, wql, bqkv, qkv_ptr,
                                          BB * SS, F3, FF);
    }

    // 2) flash attention -> bf16 hi/lo
    {
        dim3 grid(SS / 64, HH, BB);
        flash_attn<<<grid, 256, ATT_SMEM>>>(qkv_ptr, pad, ahi, alo);
    }

    // 3) out = att @ Wout + bout (mma.sync, split-bf16)
    {
        dim3 grid(FF / 128, (BB * SS) / 128);
        gemm_tc<<<grid, 256, GEMM_SMEM>>>(ahi, alo, woh, wol, bout, out,
                                          BB * SS, FF, FF);
    }
}

// round 12
// speedup vs baseline: 1.0241x; 1.0189x over previous
#include <cuda_runtime.h>
#include <cuda_bf16.h>
#include <math.h>
#include <stdint.h>

// Problem constants
#define BB 2
#define SS 4096
#define FF 768
#define HH 12
#define DD 64
#define F3 (3 * FF)

// Scratch (alloc-free rule: __device__ globals)
__device__ float g_qkv[(size_t)BB * SS * F3];                    // [B, S, 3F] fp32
__device__ __nv_bfloat16 g_xhi[(size_t)BB * SS * FF];            // x split
__device__ __nv_bfloat16 g_xlo[(size_t)BB * SS * FF];
__device__ __nv_bfloat16 g_wqkvhi[(size_t)F3 * FF];              // Wqkv^T [N=2304][K=768]
__device__ __nv_bfloat16 g_wqkvlo[(size_t)F3 * FF];
__device__ __nv_bfloat16 g_wouthi[(size_t)FF * FF];              // Wout^T [768][768]
__device__ __nv_bfloat16 g_woutlo[(size_t)FF * FF];
__device__ __nv_bfloat16 g_atthi[(size_t)BB * SS * FF];          // attention out split
__device__ __nv_bfloat16 g_attlo[(size_t)BB * SS * FF];

// ============================================================================
// Generic PTX helpers (sm_80+ features only — NO tcgen05/sm_103a-gated ops)
// ============================================================================
__device__ __forceinline__ uint32_t smem_u32(const void* p) {
    uint32_t a;
    asm("{ .reg .u64 t; cvta.to.shared.u64 t, %1; cvt.u32.u64 %0, t; }" : "=r"(a) : "l"(p));
    return a;
}

__device__ __forceinline__ void cp_async16(uint32_t saddr, const void* gaddr) {
    asm volatile("cp.async.cg.shared.global [%0], [%1], 16;" :: "r"(saddr), "l"(gaddr));
}
#define CP_COMMIT() asm volatile("cp.async.commit_group;" ::: "memory")
#define CP_WAIT(n)  asm volatile("cp.async.wait_group %0;" :: "n"(n) : "memory")

__device__ __forceinline__ void ldsm_x4(uint32_t& r0, uint32_t& r1, uint32_t& r2,
                                        uint32_t& r3, uint32_t addr) {
    asm volatile("ldmatrix.sync.aligned.m8n8.x4.shared.b16 {%0,%1,%2,%3}, [%4];"
                 : "=r"(r0), "=r"(r1), "=r"(r2), "=r"(r3) : "r"(addr));
}

__device__ __forceinline__ void mma_bf16(float* d, const uint32_t* a,
                                         uint32_t b0, uint32_t b1) {
    asm volatile(
        "mma.sync.aligned.m16n8k16.row.col.f32.bf16.bf16.f32 "
        "{%0,%1,%2,%3}, {%4,%5,%6,%7}, {%8,%9}, {%0,%1,%2,%3};"
        : "+f"(d[0]), "+f"(d[1]), "+f"(d[2]), "+f"(d[3])
        : "r"(a[0]), "r"(a[1]), "r"(a[2]), "r"(a[3]), "r"(b0), "r"(b1));
}

#define SWZ128(off) ((off) ^ (((off) >> 3) & 0x70))

__device__ __forceinline__ void split_val(float v, __nv_bfloat16& h, __nv_bfloat16& l) {
    h = __float2bfloat16_rn(v);
    l = __float2bfloat16_rn(v - __bfloat162float(h));
}

// ============================================================================
// fp32 -> (hi, lo) bf16 split, same layout. n must be %4.
// ============================================================================
__global__ __launch_bounds__(256) void split_kernel(
    const float* __restrict__ in, __nv_bfloat16* __restrict__ hi,
    __nv_bfloat16* __restrict__ lo, int n4)
{
    int idx = blockIdx.x * 256 + threadIdx.x;
    if (idx >= n4) return;
    float4 v = ((const float4*)in)[idx];
    __nv_bfloat16 h0, h1, h2, h3, l0, l1, l2, l3;
    split_val(v.x, h0, l0); split_val(v.y, h1, l1);
    split_val(v.z, h2, l2); split_val(v.w, h3, l3);
    __nv_bfloat162 ha(h0, h1), hb(h2, h3), la(l0, l1), lb(l2, l3);
    uint2 hu, lu;
    hu.x = *(uint32_t*)&ha; hu.y = *(uint32_t*)&hb;
    lu.x = *(uint32_t*)&la; lu.y = *(uint32_t*)&lb;
    ((uint2*)hi)[idx] = hu;
    ((uint2*)lo)[idx] = lu;
}

// ============================================================================
// fp32 [R][C] -> transposed bf16 hi/lo [C][R]. R,C %32. Block 32x8.
// ============================================================================
__global__ __launch_bounds__(256) void split_transpose(
    const float* __restrict__ in, __nv_bfloat16* __restrict__ hiT,
    __nv_bfloat16* __restrict__ loT, int R, int C)
{
    __shared__ float t[32][33];
    const int tx = threadIdx.x & 31;
    const int ty = threadIdx.x >> 5;   // 0..7
    const int c0 = blockIdx.x * 32;
    const int r0 = blockIdx.y * 32;
#pragma unroll
    for (int j = 0; j < 4; j++)
        t[ty + 8 * j][tx] = in[(size_t)(r0 + ty + 8 * j) * C + c0 + tx];
    __syncthreads();
#pragma unroll
    for (int j = 0; j < 4; j++) {
        float v = t[tx][ty + 8 * j];
        __nv_bfloat16 h, l;
        split_val(v, h, l);
        size_t o = (size_t)(c0 + ty + 8 * j) * R + r0 + tx;
        hiT[o] = h;
        loT[o] = l;
    }
}

// ============================================================================
// mma.sync split-bf16 GEMM: C[M,N] = (Ahi+Alo)[M,K] @ (Bhi+Blo)[N,K]^T + bias
// A, B K-major bf16. 128x128 CTA tile, 256 threads (8 warps, 2n x 4m).
// Warp tile 32(m) x 64(n). K-slab 64, cp.async double buffered, SW128 smem.
// 3 compensated MMAs per position (hi*hi + hi*lo + lo*hi).
// ============================================================================
#define GEMM_SMEM (2 * 65536)

__global__ __launch_bounds__(256, 1) void gemm_tc(
    const __nv_bfloat16* __restrict__ Ahi, const __nv_bfloat16* __restrict__ Alo,
    const __nv_bfloat16* __restrict__ Bhi, const __nv_bfloat16* __restrict__ Blo,
    const float* __restrict__ bias, float* __restrict__ C,
    int M, int N, int K)
{
    extern __shared__ __align__(1024) char sm[];
    const uint32_t smem_base = smem_u32(sm);
    const int tid  = threadIdx.x;
    const int wid  = tid >> 5;
    const int lane = tid & 31;
    const int m0 = blockIdx.y * 128;
    const int n0 = blockIdx.x * 128;
    const int wm = (wid & 3) * 32;   // warp m offset within tile
    const int wn = (wid >> 2) * 64;  // warp n offset within tile

    const int nslab = K >> 6;  // K/64

    // slab loader: 4 operand tiles [128 rows][64 bf16] SW128, cp.async 16B
    auto load_slab = [&](int s) {
        const uint32_t base = smem_base + (uint32_t)(s & 1) * 65536;
        const int k0 = s << 6;
#pragma unroll
        for (int it = 0; it < 4; it++) {
            int idx = tid + it * 256;           // 0..1023
            int row = idx >> 3;
            int ch  = idx & 7;                   // 16B chunk within 128B row
            uint32_t sw = SWZ128((uint32_t)(row * 128 + ch * 16));
            size_t ga = (size_t)(m0 + row) * K + k0 + ch * 8;
            size_t gb = (size_t)(n0 + row) * K + k0 + ch * 8;
            cp_async16(base + sw,         Ahi + ga);
            cp_async16(base + 16384 + sw, Alo + ga);
            cp_async16(base + 32768 + sw, Bhi + gb);
            cp_async16(base + 49152 + sw, Blo + gb);
        }
    };

    float acc[2][8][4];
#pragma unroll
    for (int mt = 0; mt < 2; mt++)
#pragma unroll
        for (int nt = 0; nt < 8; nt++)
#pragma unroll
            for (int e = 0; e < 4; e++) acc[mt][nt][e] = 0.f;

    // ldmatrix per-lane address components (within a [128][64bf16] SW128 tile)
    // A (x4, m16 x k16): rows m..m+15 at kb, kb+16
    const int a_row = lane & 15;
    const int a_kb  = (lane >> 4) << 4;           // 0 or 16 bytes
    // B (x4, two n8 tiles x k16): lanes 0-7 n0-7@k0 | 8-15 n0-7@k16 | 16-23 n8-15@k0 | 24-31 n8-15@k16
    const int b_row = ((lane >> 4) << 3) + (lane & 7);
    const int b_kb  = ((lane >> 3) & 1) << 4;

    load_slab(0);
    CP_COMMIT();

    for (int s = 0; s < nslab; s++) {
        if (s + 1 < nslab) {
            load_slab(s + 1);
            CP_COMMIT();
            CP_WAIT(1);
        } else {
            CP_WAIT(0);
        }
        __syncthreads();

        const uint32_t base = smem_base + (uint32_t)(s & 1) * 65536;
#pragma unroll
        for (int ks = 0; ks < 4; ks++) {
            const int kbyte = ks * 32;
            uint32_t ah[2][4], al[2][4], bh[4][4], bl[4][4];
#pragma unroll
            for (int mt = 0; mt < 2; mt++) {
                uint32_t off = SWZ128((uint32_t)((wm + mt * 16 + a_row) * 128 + kbyte + a_kb));
                ldsm_x4(ah[mt][0], ah[mt][1], ah[mt][2], ah[mt][3], base + off);
                ldsm_x4(al[mt][0], al[mt][1], al[mt][2], al[mt][3], base + 16384 + off);
            }
#pragma unroll
            for (int nt2 = 0; nt2 < 4; nt2++) {
                uint32_t off = SWZ128((uint32_t)((wn + nt2 * 16 + b_row) * 128 + kbyte + b_kb));
                ldsm_x4(bh[nt2][0], bh[nt2][1], bh[nt2][2], bh[nt2][3], base + 32768 + off);
                ldsm_x4(bl[nt2][0], bl[nt2][1], bl[nt2][2], bl[nt2][3], base + 49152 + off);
            }
#pragma unroll
            for (int mt = 0; mt < 2; mt++)
#pragma unroll
                for (int nt = 0; nt < 8; nt++) {
                    const int q = nt >> 1, r = (nt & 1) << 1;
                    mma_bf16(acc[mt][nt], ah[mt], bh[q][r], bh[q][r + 1]);  // hi*hi
                    mma_bf16(acc[mt][nt], ah[mt], bl[q][r], bl[q][r + 1]);  // hi*lo
                    mma_bf16(acc[mt][nt], al[mt], bh[q][r], bh[q][r + 1]);  // lo*hi
                }
        }
        __syncthreads();  // all warps done reading buffer s before slab s+2 load
    }

    // Epilogue: acc fragment -> C with bias. d0,d1: row=lane/4, col=2*(lane%4);
    // d2,d3: row+8.
    const int erow = lane >> 2;
    const int ecol = (lane & 3) << 1;
#pragma unroll
    for (int mt = 0; mt < 2; mt++) {
#pragma unroll
        for (int nt = 0; nt < 8; nt++) {
            const int gc = n0 + wn + nt * 8 + ecol;
            const int gr = m0 + wm + mt * 16 + erow;
            float2 v0, v1;
            v0.x = acc[mt][nt][0] + bias[gc];
            v0.y = acc[mt][nt][1] + bias[gc + 1];
            v1.x = acc[mt][nt][2] + bias[gc];
            v1.y = acc[mt][nt][3] + bias[gc + 1];
            *(float2*)(C + (size_t)gr * N + gc)       = v0;
            *(float2*)(C + (size_t)(gr + 8) * N + gc) = v1;
        }
    }
}

// ============================================================================
// Flash attention (fp32 SIMT, round-3 proven); epilogue writes bf16 hi/lo.
// ============================================================================
#define ATT_SMEM (4 * 64 * 65 * sizeof(float))

__global__ __launch_bounds__(256) void flash_attn(
    const float* __restrict__ qkv, const unsigned char* __restrict__ pad,
    __nv_bfloat16* __restrict__ outhi, __nv_bfloat16* __restrict__ outlo)
{
    extern __shared__ float smf[];
    float* Qs = smf;
    float* Ks = Qs + 64 * 65;
    float* Vs = Ks + 64 * 65;
    float* Ps = Vs + 64 * 65;
    __shared__ unsigned char padf[64];

    const int qt = (gridDim.x - 1) - blockIdx.x;
    const int h  = blockIdx.y;
    const int b  = blockIdx.z;
    const int tid = threadIdx.x;
    const int ty  = tid >> 4;
    const int tx  = tid & 15;
    const float scale = 0.125f;
    const size_t base = (size_t)b * SS * F3;
    const int q0 = qt * 64;

    for (int i = tid; i < 64 * 16; i += 256) {
        int r  = i >> 4;
        int c4 = (i & 15) << 2;
        float4 v = *(const float4*)(qkv + base + (size_t)(q0 + r) * F3 + h * DD + c4);
        Qs[r * 65 + c4 + 0] = v.x * scale;
        Qs[r * 65 + c4 + 1] = v.y * scale;
        Qs[r * 65 + c4 + 2] = v.z * scale;
        Qs[r * 65 + c4 + 3] = v.w * scale;
    }

    float m[4], l[4], o[4][4];
#pragma unroll
    for (int i = 0; i < 4; i++) {
        m[i] = -1e30f; l[i] = 0.f;
#pragma unroll
        for (int j = 0; j < 4; j++) o[i][j] = 0.f;
    }

    for (int kt = 0; kt <= qt; kt++) {
        const int k0 = kt * 64;
        __syncthreads();
        for (int i = tid; i < 64 * 16; i += 256) {
            int r  = i >> 4;
            int c4 = (i & 15) << 2;
            float4 kv = *(const float4*)(qkv + base + (size_t)(k0 + r) * F3 + FF + h * DD + c4);
            Ks[r * 65 + c4 + 0] = kv.x;
            Ks[r * 65 + c4 + 1] = kv.y;
            Ks[r * 65 + c4 + 2] = kv.z;
            Ks[r * 65 + c4 + 3] = kv.w;
            float4 vv = *(const float4*)(qkv + base + (size_t)(k0 + r) * F3 + 2 * FF + h * DD + c4);
            Vs[r * 65 + c4 + 0] = vv.x;
            Vs[r * 65 + c4 + 1] = vv.y;
            Vs[r * 65 + c4 + 2] = vv.z;
            Vs[r * 65 + c4 + 3] = vv.w;
        }
        if (tid < 64) padf[tid] = pad[(size_t)b * SS + k0 + tid];
        __syncthreads();

        float acc[4][4];
#pragma unroll
        for (int i = 0; i < 4; i++)
#pragma unroll
            for (int j = 0; j < 4; j++) acc[i][j] = 0.f;

#pragma unroll 8
        for (int d = 0; d < 64; d++) {
            float ar[4], br[4];
#pragma unroll
            for (int i = 0; i < 4; i++) ar[i] = Qs[(4 * ty + i) * 65 + d];
#pragma unroll
            for (int j = 0; j < 4; j++) br[j] = Ks[(4 * tx + j) * 65 + d];
#pragma unroll
            for (int i = 0; i < 4; i++)
#pragma unroll
                for (int j = 0; j < 4; j++) acc[i][j] += ar[i] * br[j];
        }

        const bool diag = (kt == qt);
#pragma unroll
        for (int j = 0; j < 4; j++) {
            const int kj = 4 * tx + j;
            const bool padded = padf[kj] != 0;
#pragma unroll
            for (int i = 0; i < 4; i++) {
                const int qi = 4 * ty + i;
                if ((diag && kj > qi) || padded) acc[i][j] = -1e30f;
            }
        }

        float mnew[4];
#pragma unroll
        for (int i = 0; i < 4; i++) {
            float rm = fmaxf(fmaxf(acc[i][0], acc[i][1]), fmaxf(acc[i][2], acc[i][3]));
#pragma unroll
            for (int off = 8; off >= 1; off >>= 1)
                rm = fmaxf(rm, __shfl_xor_sync(0xffffffffu, rm, off));
            mnew[i] = fmaxf(m[i], rm);
            float alpha = __expf(m[i] - mnew[i]);
            m[i] = mnew[i];
            float rs = 0.f;
#pragma unroll
            for (int j = 0; j < 4; j++) {
                float p = __expf(acc[i][j] - mnew[i]);
                acc[i][j] = p;
                rs += p;
            }
#pragma unroll
            for (int off = 8; off >= 1; off >>= 1)
                rs += __shfl_xor_sync(0xffffffffu, rs, off);
            l[i] = l[i] * alpha + rs;
#pragma unroll
            for (int j = 0; j < 4; j++) o[i][j] *= alpha;
        }

#pragma unroll
        for (int i = 0; i < 4; i++)
#pragma unroll
            for (int j = 0; j < 4; j++)
                Ps[(4 * ty + i) * 65 + 4 * tx + j] = acc[i][j];
        __syncthreads();

#pragma unroll 8
        for (int n = 0; n < 64; n++) {
            float ar[4], br[4];
#pragma unroll
            for (int i = 0; i < 4; i++) ar[i] = Ps[(4 * ty + i) * 65 + n];
#pragma unroll
            for (int j = 0; j < 4; j++) br[j] = Vs[n * 65 + 4 * tx + j];
#pragma unroll
            for (int i = 0; i < 4; i++)
#pragma unroll
                for (int j = 0; j < 4; j++) o[i][j] += ar[i] * br[j];
        }
    }

    // Epilogue: normalize + split to bf16 hi/lo
#pragma unroll
    for (int i = 0; i < 4; i++) {
        const float invl = 1.0f / l[i];
        __nv_bfloat16 hh[4], ll[4];
#pragma unroll
        for (int j = 0; j < 4; j++) {
            float v = o[i][j] * invl;
            split_val(v, hh[j], ll[j]);
        }
        __nv_bfloat162 ha(hh[0], hh[1]), hb(hh[2], hh[3]);
        __nv_bfloat162 la(ll[0], ll[1]), lb(ll[2], ll[3]);
        uint2 hu, lu;
        hu.x = *(uint32_t*)&ha; hu.y = *(uint32_t*)&hb;
        lu.x = *(uint32_t*)&la; lu.y = *(uint32_t*)&lb;
        size_t off = (size_t)b * SS * FF + (size_t)(q0 + 4 * ty + i) * FF + h * DD + 4 * tx;
        *(uint2*)(outhi + off) = hu;
        *(uint2*)(outlo + off) = lu;
    }
}

// ============================================================================
extern "C" void kernel_launch(void* const* d_in, const int* in_sizes, int n_in,
                              void* d_out, int out_size)
{
    const float*         x    = (const float*)d_in[0];
    const unsigned char* pad  = (const unsigned char*)d_in[1];
    const float*         Wqkv = (const float*)d_in[2];
    const float*         bqkv = (const float*)d_in[3];
    const float*         Wout = (const float*)d_in[4];
    const float*         bout = (const float*)d_in[5];
    float*               out  = (float*)d_out;

    float *qkv_ptr;
    __nv_bfloat16 *xhi, *xlo, *wqh, *wql, *woh, *wol, *ahi, *alo;
    cudaGetSymbolAddress((void**)&qkv_ptr, g_qkv);
    cudaGetSymbolAddress((void**)&xhi, g_xhi);
    cudaGetSymbolAddress((void**)&xlo, g_xlo);
    cudaGetSymbolAddress((void**)&wqh, g_wqkvhi);
    cudaGetSymbolAddress((void**)&wql, g_wqkvlo);
    cudaGetSymbolAddress((void**)&woh, g_wouthi);
    cudaGetSymbolAddress((void**)&wol, g_woutlo);
    cudaGetSymbolAddress((void**)&ahi, g_atthi);
    cudaGetSymbolAddress((void**)&alo, g_attlo);

    cudaFuncSetAttribute(gemm_tc, cudaFuncAttributeMaxDynamicSharedMemorySize, GEMM_SMEM);
    cudaFuncSetAttribute(flash_attn, cudaFuncAttributeMaxDynamicSharedMemorySize, (int)ATT_SMEM);

    // 0) splits
    {
        int n4 = (BB * SS * FF) / 4;
        split_kernel<<<(n4 + 255) / 256, 256>>>(x, xhi, xlo, n4);
        dim3 g1(F3 / 32, FF / 32);
        split_transpose<<<g1, 256>>>(Wqkv, wqh, wql, FF, F3);
        dim3 g2(FF / 32, FF / 32);
        split_transpose<<<g2, 256>>>(Wout, woh, wol, FF, FF);
    }

    // 1) qkv = x @ Wqkv + bqkv (mma.sync, split-bf16)
    {
        dim3 grid(F3 / 128, (BB * SS) / 128);
        gemm_tc<<<grid, 256, GEMM_SMEM>>>(xhi, xlo, wqh, wql, bqkv, qkv_ptr,
                                          BB * SS, F3, FF);
    }

    // 2) flash attention -> bf16 hi/lo
    {
        dim3 grid(SS / 64, HH, BB);
        flash_attn<<<grid, 256, ATT_SMEM>>>(qkv_ptr, pad, ahi, alo);
    }

    // 3) out = att @ Wout + bout (mma.sync, split-bf16)
    {
        dim3 grid(FF / 128, (BB * SS) / 128);
        gemm_tc<<<grid, 256, GEMM_SMEM>>>(ahi, alo, woh, wol, bout, out,
                                          BB * SS, FF, FF);
    }
}